// round 5
// baseline (speedup 1.0000x reference)
#include <cuda_runtime.h>
#include <cstdint>

#define GN    8192
#define LMBD  0.1f
#define ROWS  8          // rows per block
#define QCAP  32         // float4-entries per warp-chunk queue (incl 3 sentinels)
#define QCAP3 (QCAP - 3)
#define FULLM 0xffffffffu

__device__ float    g_sum;     // zero-init; reset by last block each launch
__device__ unsigned g_count;

// Block handles 8 consecutive rows of A. Warp w owns cols [w*1024,(w+1)*1024)
// of each row, scanned in 2 chunks of 4 float4/lane. Nonzero float4s are
// compacted (1 ballot / 128 floats) into a per-warp smem queue and drained
// 4-at-a-time: the warp's four 8-lane groups each take one entry, extract its
// first nonzero component, and compute Y[i].W[j] cooperatively (lane holds 16
// elems of the row, 3-stage shuffle reduce). b folded: p = W[j].Y[i] + b.Y[i].
// Next chunk's A loads are always in flight during compact+drain.
__global__ void __launch_bounds__(256, 5)
main_kernel(const float* __restrict__ A, const float* __restrict__ W,
            const float* __restrict__ b, float* __restrict__ out) {
    __shared__ float4 qa4[8][QCAP];
    __shared__ int    qj[8][QCAP];
    __shared__ float  sp[8];

    const int w    = threadIdx.x >> 5;
    const int lane = threadIdx.x & 31;
    const int gl   = lane & 7;     // lane in 8-lane group
    const int grp  = lane >> 3;    // group 0..3
    const unsigned ltm = (1u << lane) - 1u;

    const float4* __restrict__ W4 = reinterpret_cast<const float4*>(W);
    const float4* __restrict__ B4 = reinterpret_cast<const float4*>(b);
    const float4* __restrict__ A4 = reinterpret_cast<const float4*>(A);

    const int row0  = blockIdx.x * ROWS;
    const int base4 = w * 256;                  // warp's float4 base in a row

    float acc = 0.f;
    float4 yi[4];
    float  ci = 0.f;

    // group-cooperative dot of current yi with W-row j (+ci fold done by caller)
    auto gdot = [&](int j) -> float {
        const float4* yr = W4 + j * 32 + gl;
        float4 z0 = yr[0], z1 = yr[8], z2 = yr[16], z3 = yr[24];
        float p = z0.x*yi[0].x + z0.y*yi[0].y + z0.z*yi[0].z + z0.w*yi[0].w;
        p += z1.x*yi[1].x + z1.y*yi[1].y + z1.z*yi[1].z + z1.w*yi[1].w;
        p += z2.x*yi[2].x + z2.y*yi[2].y + z2.z*yi[2].z + z2.w*yi[2].w;
        p += z3.x*yi[3].x + z3.y*yi[3].y + z3.z*yi[3].z + z3.w*yi[3].w;
        p += __shfl_xor_sync(FULLM, p, 1);
        p += __shfl_xor_sync(FULLM, p, 2);
        p += __shfl_xor_sync(FULLM, p, 4);
        return p;
    };

    float4 av[4];
    // prologue: issue first chunk loads (row0, chunk0)
    {
        const float4* ap = A4 + (size_t)row0 * 2048 + base4;
        #pragma unroll
        for (int k = 0; k < 4; k++) av[k] = __ldcs(ap + k * 32 + lane);
    }

    for (int r = 0; r < ROWS; r++) {
        const int row = row0 + r;

        // yi = W[row]+b (16 elems/lane, replicated across groups); ci=b.yi, rn=|yi|^2
        float rn = 0.f;
        ci = 0.f;
        #pragma unroll
        for (int i = 0; i < 4; i++) {
            float4 wv = W4[row * 32 + i * 8 + gl];
            float4 bv = B4[i * 8 + gl];
            yi[i].x = wv.x + bv.x; yi[i].y = wv.y + bv.y;
            yi[i].z = wv.z + bv.z; yi[i].w = wv.w + bv.w;
            ci += bv.x*yi[i].x + bv.y*yi[i].y + bv.z*yi[i].z + bv.w*yi[i].w;
            rn += yi[i].x*yi[i].x + yi[i].y*yi[i].y
                + yi[i].z*yi[i].z + yi[i].w*yi[i].w;
        }
        #pragma unroll
        for (int off = 1; off < 8; off <<= 1) {
            ci += __shfl_xor_sync(FULLM, ci, off);
            rn += __shfl_xor_sync(FULLM, rn, off);
        }
        if (w == 0 && lane == 0) acc = fmaf(0.5f * LMBD, rn, acc);

        #pragma unroll
        for (int c = 0; c < 2; c++) {
            int cnt = 0;

            // ---- compact current chunk (av) into the queue ----
            #pragma unroll
            for (int k = 0; k < 4; k++) {
                float4 a4 = av[k];
                uint4 u; u.x = __float_as_uint(a4.x); u.y = __float_as_uint(a4.y);
                         u.z = __float_as_uint(a4.z); u.w = __float_as_uint(a4.w);
                bool nz = ((u.x | u.y) | (u.z | u.w)) != 0u;  // A >= 0
                unsigned m = __ballot_sync(FULLM, nz);
                if (m) {
                    int g4  = base4 + c * 128 + k * 32 + lane;
                    int n   = __popc(m);
                    int pos = cnt + __popc(m & ltm);
                    if (nz && pos < QCAP3) { qa4[w][pos] = a4; qj[w][pos] = g4; }
                    if (cnt + n > QCAP3) {   // overflow: inline (never expected)
                        unsigned mo = __ballot_sync(FULLM, nz && pos >= QCAP3);
                        while (mo) {
                            int src = __ffs(mo) - 1; mo &= mo - 1;
                            float bx = __shfl_sync(FULLM, a4.x, src);
                            float by = __shfl_sync(FULLM, a4.y, src);
                            float bz = __shfl_sync(FULLM, a4.z, src);
                            float bw = __shfl_sync(FULLM, a4.w, src);
                            int   jb = __shfl_sync(FULLM, g4, src) * 4;
                            #pragma unroll
                            for (int e = 0; e < 4; e++) {
                                float a = (e==0)?bx:(e==1)?by:(e==2)?bz:bw;
                                if (a > 0.f) {
                                    float p = gdot(jb + e);
                                    if (lane == 0) {
                                        float rr = a - (p + ci);
                                        acc = fmaf(0.5f * rr, rr, acc);
                                    }
                                }
                            }
                        }
                    }
                    cnt = min(cnt + n, QCAP3);
                }
            }

            // ---- issue next chunk loads (overlap DRAM with drain) ----
            {
                int nr = row, nc = c + 1;
                if (nc == 2) { nr = row + 1; nc = 0; }
                if (nr < row0 + ROWS) {
                    const float4* ap = A4 + (size_t)nr * 2048 + base4 + nc * 128;
                    #pragma unroll
                    for (int k = 0; k < 4; k++) av[k] = __ldcs(ap + k * 32 + lane);
                }
            }

            // sentinels (a4.x = -1 gates everything off; j=0 keeps loads legal)
            if (lane < 3) {
                qa4[w][cnt + lane] = make_float4(-1.f, -1.f, -1.f, -1.f);
                qj[w][cnt + lane] = 0;
            }
            __syncwarp();

            // ---- drain: 4 entries per step, one per 8-lane group ----
            for (int base = 0; base < cnt; base += 4) {
                int    idx = base + grp;
                float4 a4  = qa4[w][idx];      // group-broadcast
                int    jb4 = qj[w][idx];
                unsigned nzm = (a4.x > 0.f ? 1u : 0u) | (a4.y > 0.f ? 2u : 0u)
                             | (a4.z > 0.f ? 4u : 0u) | (a4.w > 0.f ? 8u : 0u);
                int e0 = __ffs(nzm) - 1;                    // -1 for sentinel
                float a = (e0 <= 0) ? a4.x : (e0 == 1) ? a4.y
                        : (e0 == 2) ? a4.z : a4.w;
                int j = jb4 * 4 + max(e0, 0);
                float p = gdot(j);
                if (nzm && gl == 0) {
                    float rr = a - (p + ci);
                    acc = fmaf(0.5f * rr, rr, acc);
                }
                // rare: more than one nonzero component in this float4
                unsigned rem = nzm & (nzm - 1u);
                while (__any_sync(FULLM, rem != 0u)) {
                    bool act = rem != 0u;
                    int e = __ffs(rem) - 1;
                    float a2 = (e == 1) ? a4.y : (e == 2) ? a4.z : a4.w;
                    int j2 = act ? (jb4 * 4 + e) : 0;
                    float q = gdot(j2);
                    if (act && gl == 0) {
                        float rr = a2 - (q + ci);
                        acc = fmaf(0.5f * rr, rr, acc);
                    }
                    rem &= rem - 1u;
                }
            }
            __syncwarp();   // queue reads done before next chunk overwrites
        }
    }

    // block reduce (acc lives on gl==0 lanes; groups hold distinct sums)
    #pragma unroll
    for (int off = 16; off > 0; off >>= 1)
        acc += __shfl_xor_sync(FULLM, acc, off);
    if (lane == 0) sp[w] = acc;
    __syncthreads();

    if (threadIdx.x == 0) {
        float part = 0.f;
        #pragma unroll
        for (int i = 0; i < 8; i++) part += sp[i];
        atomicAdd(&g_sum, part);
        __threadfence();
        unsigned cdone = atomicAdd(&g_count, 1u);
        if (cdone == gridDim.x - 1) {
            float total = atomicExch(&g_sum, 0.f);
            atomicExch(&g_count, 0u);
            out[0] = total;
        }
    }
}

extern "C" void kernel_launch(void* const* d_in, const int* in_sizes, int n_in,
                              void* d_out, int out_size) {
    const float* A = (const float*)d_in[0];
    const float* W = (const float*)d_in[1];
    const float* b = (const float*)d_in[2];
    float* out = (float*)d_out;

    main_kernel<<<GN / ROWS, 256>>>(A, W, b, out);
}

// round 6
// speedup vs baseline: 1.1317x; 1.1317x over previous
#include <cuda_runtime.h>
#include <cstdint>

#define GN    8192
#define LMBD  0.1f
#define QCAP  64      // scalar queue entries per warp (per chunk); E[nz/chunk]=5.1
#define QEFF  (QCAP - 3)
#define FULLM 0xffffffffu

__device__ float    g_sum;     // zero-init; reset by last block each launch
__device__ unsigned g_count;

// One block per row of A (8192 x 256). Warp w owns cols [w*1024,(w+1)*1024),
// scanned as 2 chunks of 4 float4/lane (next chunk's loads always in flight).
// Compaction: 1 ballot per float4 (A>=0 so OR of raw bits != 0 <=> any nz);
// the first nonzero component is pre-extracted and queued as scalar (a, j).
// Rare extra components (P~1.5%) are handled inline with an all-lane group dot.
// Drain: 4 queue entries per step, one per 8-lane group; each lane holds 16
// elems of Y[row] (stride-8 float4s -> 128B coalesced W loads), 3-shfl reduce.
// b folded algebraically: pred = W[j].Y[i] + b.Y[i].
__global__ void __launch_bounds__(256, 5)
main_kernel(const float* __restrict__ A, const float* __restrict__ W,
            const float* __restrict__ b, float* __restrict__ out) {
    __shared__ float qa[8][QCAP];
    __shared__ int   qj[8][QCAP];
    __shared__ float sp[8];

    const int row  = blockIdx.x;
    const int w    = threadIdx.x >> 5;
    const int lane = threadIdx.x & 31;
    const int gl   = lane & 7;
    const int grp  = lane >> 3;
    const unsigned ltm = (1u << lane) - 1u;

    const float4* __restrict__ A4 =
        reinterpret_cast<const float4*>(A) + (size_t)row * (GN / 4);
    const float4* __restrict__ W4 = reinterpret_cast<const float4*>(W);
    const float4* __restrict__ B4 = reinterpret_cast<const float4*>(b);

    // yi = W[row]+b, 16 elems/lane (float4 indices gl, gl+8, gl+16, gl+24),
    // replicated across the 4 groups. ci = b.yi, rn = ||yi||^2.
    float4 yi[4];
    float ci = 0.f, rn = 0.f;
    #pragma unroll
    for (int i = 0; i < 4; i++) {
        float4 wv = W4[row * 32 + i * 8 + gl];
        float4 bv = B4[i * 8 + gl];
        yi[i].x = wv.x + bv.x; yi[i].y = wv.y + bv.y;
        yi[i].z = wv.z + bv.z; yi[i].w = wv.w + bv.w;
        ci += bv.x*yi[i].x + bv.y*yi[i].y + bv.z*yi[i].z + bv.w*yi[i].w;
        rn += yi[i].x*yi[i].x + yi[i].y*yi[i].y
            + yi[i].z*yi[i].z + yi[i].w*yi[i].w;
    }
    #pragma unroll
    for (int off = 1; off < 8; off <<= 1) {
        ci += __shfl_xor_sync(FULLM, ci, off);
        rn += __shfl_xor_sync(FULLM, rn, off);
    }

    // group-cooperative dot with W-row j; if all lanes pass the same j, every
    // group computes the full dot -> result valid on all 32 lanes.
    auto gdot = [&](int j) -> float {
        const float4* yr = W4 + j * 32 + gl;
        float4 z0 = yr[0], z1 = yr[8], z2 = yr[16], z3 = yr[24];
        float p = z0.x*yi[0].x + z0.y*yi[0].y + z0.z*yi[0].z + z0.w*yi[0].w;
        p += z1.x*yi[1].x + z1.y*yi[1].y + z1.z*yi[1].z + z1.w*yi[1].w;
        p += z2.x*yi[2].x + z2.y*yi[2].y + z2.z*yi[2].z + z2.w*yi[2].w;
        p += z3.x*yi[3].x + z3.y*yi[3].y + z3.z*yi[3].z + z3.w*yi[3].w;
        p += __shfl_xor_sync(FULLM, p, 1);
        p += __shfl_xor_sync(FULLM, p, 2);
        p += __shfl_xor_sync(FULLM, p, 4);
        return p;
    };

    float acc = 0.f;
    if (w == 0 && lane == 0) acc = 0.5f * LMBD * rn;

    const int base4 = w * 256;
    int cnt = 0;   // warp-uniform

    // compact one float4 (first nz queued; extras + overflow handled inline)
    auto compact = [&](float4 a4, int g4) {
        unsigned ux = __float_as_uint(a4.x), uy = __float_as_uint(a4.y);
        unsigned uz = __float_as_uint(a4.z), uw = __float_as_uint(a4.w);
        bool nz = ((ux | uy) | (uz | uw)) != 0u;   // A >= 0
        unsigned m = __ballot_sync(FULLM, nz);
        if (m == 0) return;

        unsigned nzm = (a4.x > 0.f ? 1u : 0u) | (a4.y > 0.f ? 2u : 0u)
                     | (a4.z > 0.f ? 4u : 0u) | (a4.w > 0.f ? 8u : 0u);
        int e0 = __ffs(nzm) - 1;                   // valid when nz
        float a0 = (e0 <= 0) ? a4.x : (e0 == 1) ? a4.y
                 : (e0 == 2) ? a4.z : a4.w;
        int pos = cnt + __popc(m & ltm);
        if (nz && pos < QEFF) { qa[w][pos] = a0; qj[w][pos] = g4 * 4 + e0; }

        // overflow (never expected) + extra components (rare): inline
        unsigned extra = nz ? (nzm & (nzm - 1u)) : 0u;
        unsigned mo = __ballot_sync(FULLM, (extra != 0u) | (nz && pos >= QEFF));
        cnt = min(cnt + __popc(m), QEFF);
        while (mo) {
            int src = __ffs(mo) - 1; mo &= mo - 1;
            float bx = __shfl_sync(FULLM, a4.x, src);
            float by = __shfl_sync(FULLM, a4.y, src);
            float bz = __shfl_sync(FULLM, a4.z, src);
            float bw = __shfl_sync(FULLM, a4.w, src);
            unsigned em = __shfl_sync(FULLM, extra, src);
            bool ovf = __shfl_sync(FULLM, (int)(nz && pos >= QEFF), src);
            unsigned nm = __shfl_sync(FULLM, nzm, src);
            int jb = __shfl_sync(FULLM, g4, src) * 4;
            unsigned todo = ovf ? nm : em;
            while (todo) {
                int e = __ffs(todo) - 1; todo &= todo - 1;
                float a = (e == 0) ? bx : (e == 1) ? by : (e == 2) ? bz : bw;
                float p = gdot(jb + e);
                if (lane == 0) {
                    float rr = a - (p + ci);
                    acc = fmaf(0.5f * rr, rr, acc);
                }
            }
        }
    };

    auto drain = [&]() {
        int cntp = (cnt + 3) & ~3;
        if (lane < cntp - cnt) { qa[w][cnt + lane] = 0.f; qj[w][cnt + lane] = 0; }
        __syncwarp();
        for (int base = 0; base < cntp; base += 4) {
            float a = qa[w][base + grp];   // group-broadcast smem reads
            int   j = qj[w][base + grp];
            float p = gdot(j);
            if (a > 0.f && gl == 0) {
                float rr = a - (p + ci);
                acc = fmaf(0.5f * rr, rr, acc);
            }
        }
        __syncwarp();
        cnt = 0;
    };

    float4 av[4];
    // chunk 0 loads (streaming; A read exactly once)
    #pragma unroll
    for (int k = 0; k < 4; k++) av[k] = __ldcs(A4 + base4 + k * 32 + lane);
    #pragma unroll
    for (int k = 0; k < 4; k++) compact(av[k], base4 + k * 32 + lane);
    // chunk 1 loads in flight before draining chunk 0
    #pragma unroll
    for (int k = 0; k < 4; k++) av[k] = __ldcs(A4 + base4 + 128 + k * 32 + lane);
    drain();
    #pragma unroll
    for (int k = 0; k < 4; k++) compact(av[k], base4 + 128 + k * 32 + lane);
    drain();

    // block reduce
    #pragma unroll
    for (int off = 16; off > 0; off >>= 1)
        acc += __shfl_xor_sync(FULLM, acc, off);
    if (lane == 0) sp[w] = acc;
    __syncthreads();

    if (threadIdx.x == 0) {
        float part = 0.f;
        #pragma unroll
        for (int i = 0; i < 8; i++) part += sp[i];
        atomicAdd(&g_sum, part);
        __threadfence();
        unsigned c = atomicAdd(&g_count, 1u);
        if (c == gridDim.x - 1) {
            float total = atomicExch(&g_sum, 0.f);
            atomicExch(&g_count, 0u);
            out[0] = total;
        }
    }
}

extern "C" void kernel_launch(void* const* d_in, const int* in_sizes, int n_in,
                              void* d_out, int out_size) {
    const float* A = (const float*)d_in[0];
    const float* W = (const float*)d_in[1];
    const float* b = (const float*)d_in[2];
    float* out = (float*)d_out;

    main_kernel<<<GN, 256>>>(A, W, b, out);
}

// round 7
// speedup vs baseline: 1.6477x; 1.4560x over previous
#include <cuda_runtime.h>
#include <cstdint>

#define GN    8192
#define LMBD  0.1f
#define QCAP  64
#define QEFF  (QCAP - 4)
#define FULLM 0xffffffffu

__device__ float    g_sum;     // zero-init; reset by last block each launch
__device__ unsigned g_count;

// One block per row of A (8192 x 256). Warp w owns cols [w*1024,(w+1)*1024),
// scanned as 2 chunks of 4 float4/lane; chunk-1 loads are in flight during
// drain of chunk 0. Compaction: 1 ballot per float4 (first nz queued as
// scalar (a, j)); rare extra components / overflow handled inline.
// Drain: 16-lane dot groups (lane holds 8 elems of Y[row]); each iteration
// processes 4 queue entries with ALL 8 W-loads issued before any reduce
// (A/B pipeline) -> L2 latency amortized 4x. 4-shfl reduce per dot.
// b folded algebraically: pred = W[j].Y[i] + b.Y[i].
__global__ void __launch_bounds__(256, 5)
main_kernel(const float* __restrict__ A, const float* __restrict__ W,
            const float* __restrict__ b, float* __restrict__ out) {
    __shared__ float qa[8][QCAP];
    __shared__ int   qj[8][QCAP];
    __shared__ float sp[8];

    const int row  = blockIdx.x;
    const int w    = threadIdx.x >> 5;
    const int lane = threadIdx.x & 31;
    const int hl   = lane & 15;    // lane within 16-lane group
    const int grp  = lane >> 4;    // group 0..1
    const unsigned ltm = (1u << lane) - 1u;

    const float4* __restrict__ A4 =
        reinterpret_cast<const float4*>(A) + (size_t)row * (GN / 4);
    const float4* __restrict__ W4 = reinterpret_cast<const float4*>(W);
    const float4* __restrict__ B4 = reinterpret_cast<const float4*>(b);

    // yi = W[row]+b: lane holds float4 indices {hl, hl+16} (8 elems),
    // replicated across the 2 groups. ci = b.yi, rn = ||yi||^2.
    float4 yi0, yi1;
    float ci, rn;
    {
        float4 wv0 = W4[row * 32 + hl],      bv0 = B4[hl];
        float4 wv1 = W4[row * 32 + 16 + hl], bv1 = B4[16 + hl];
        yi0.x = wv0.x + bv0.x; yi0.y = wv0.y + bv0.y;
        yi0.z = wv0.z + bv0.z; yi0.w = wv0.w + bv0.w;
        yi1.x = wv1.x + bv1.x; yi1.y = wv1.y + bv1.y;
        yi1.z = wv1.z + bv1.z; yi1.w = wv1.w + bv1.w;
        ci = bv0.x*yi0.x + bv0.y*yi0.y + bv0.z*yi0.z + bv0.w*yi0.w
           + bv1.x*yi1.x + bv1.y*yi1.y + bv1.z*yi1.z + bv1.w*yi1.w;
        rn = yi0.x*yi0.x + yi0.y*yi0.y + yi0.z*yi0.z + yi0.w*yi0.w
           + yi1.x*yi1.x + yi1.y*yi1.y + yi1.z*yi1.z + yi1.w*yi1.w;
        #pragma unroll
        for (int off = 1; off < 16; off <<= 1) {
            ci += __shfl_xor_sync(FULLM, ci, off);
            rn += __shfl_xor_sync(FULLM, rn, off);
        }
    }

    // reduce 8 per-lane products over the 16-lane group (valid on all lanes)
    auto dot8 = [&](float4 z0, float4 z1) -> float {
        float p = z0.x*yi0.x + z0.y*yi0.y + z0.z*yi0.z + z0.w*yi0.w
                + z1.x*yi1.x + z1.y*yi1.y + z1.z*yi1.z + z1.w*yi1.w;
        p += __shfl_xor_sync(FULLM, p, 1);
        p += __shfl_xor_sync(FULLM, p, 2);
        p += __shfl_xor_sync(FULLM, p, 4);
        p += __shfl_xor_sync(FULLM, p, 8);
        return p;
    };

    float acc = (w == 0 && lane == 0) ? 0.5f * LMBD * rn : 0.f;

    const int base4 = w * 256;
    int cnt = 0;   // warp-uniform

    // compact one float4: queue first nz as scalar; extras/overflow inline
    auto compact = [&](float4 a4, int g4) {
        unsigned nzm = (a4.x > 0.f ? 1u : 0u) | (a4.y > 0.f ? 2u : 0u)
                     | (a4.z > 0.f ? 4u : 0u) | (a4.w > 0.f ? 8u : 0u);
        bool nz = nzm != 0u;
        unsigned m = __ballot_sync(FULLM, nz);
        if (m == 0) return;

        int e0 = __ffs(nzm) - 1;
        float a0 = (e0 <= 0) ? a4.x : (e0 == 1) ? a4.y
                 : (e0 == 2) ? a4.z : a4.w;
        int pos = cnt + __popc(m & ltm);
        bool ovf = nz && pos >= QEFF;
        if (nz && !ovf) { qa[w][pos] = a0; qj[w][pos] = g4 * 4 + e0; }

        unsigned extra = nz ? (nzm & (nzm - 1u)) : 0u;
        unsigned mo = __ballot_sync(FULLM, (extra != 0u) | ovf);
        cnt = min(cnt + __popc(m), QEFF);
        while (mo) {   // rare
            int src = __ffs(mo) - 1; mo &= mo - 1;
            float bx = __shfl_sync(FULLM, a4.x, src);
            float by = __shfl_sync(FULLM, a4.y, src);
            float bz = __shfl_sync(FULLM, a4.z, src);
            float bw = __shfl_sync(FULLM, a4.w, src);
            unsigned em = __shfl_sync(FULLM, extra, src);
            unsigned nm = __shfl_sync(FULLM, nzm, src);
            int  ov = __shfl_sync(FULLM, (int)ovf, src);
            int  jb = __shfl_sync(FULLM, g4, src) * 4;
            unsigned todo = ov ? nm : em;
            while (todo) {
                int e = __ffs(todo) - 1; todo &= todo - 1;
                float a = (e == 0) ? bx : (e == 1) ? by : (e == 2) ? bz : bw;
                const float4* yr = W4 + (jb + e) * 32 + hl;
                float p = dot8(yr[0], yr[16]);   // same j both groups -> full dot
                if (lane == 0) {
                    float rr = a - (p + ci);
                    acc = fmaf(0.5f * rr, rr, acc);
                }
            }
        }
    };

    // drain queue: 4 entries per iteration, all 8 W-loads before any reduce
    auto drain = [&]() {
        int cntp = (cnt + 3) & ~3;
        if (lane < cntp - cnt) { qa[w][cnt + lane] = 0.f; qj[w][cnt + lane] = 0; }
        __syncwarp();
        for (int base = 0; base < cntp; base += 4) {
            float aA = qa[w][base + grp];       int jA = qj[w][base + grp];
            float aB = qa[w][base + 2 + grp];   int jB = qj[w][base + 2 + grp];
            const float4* ya = W4 + jA * 32 + hl;
            const float4* yb = W4 + jB * 32 + hl;
            float4 za0 = ya[0],  za1 = ya[16];
            float4 zb0 = yb[0],  zb1 = yb[16];
            float pA = dot8(za0, za1);
            if (aA > 0.f && hl == 0) {
                float rr = aA - (pA + ci);
                acc = fmaf(0.5f * rr, rr, acc);
            }
            float pB = dot8(zb0, zb1);
            if (aB > 0.f && hl == 0) {
                float rr = aB - (pB + ci);
                acc = fmaf(0.5f * rr, rr, acc);
            }
        }
        __syncwarp();
        cnt = 0;
    };

    float4 av[4];
    // chunk 0 loads (streaming; A read exactly once)
    #pragma unroll
    for (int k = 0; k < 4; k++) av[k] = __ldcs(A4 + base4 + k * 32 + lane);
    #pragma unroll
    for (int k = 0; k < 4; k++) compact(av[k], base4 + k * 32 + lane);
    // chunk 1 loads in flight before draining chunk 0
    #pragma unroll
    for (int k = 0; k < 4; k++) av[k] = __ldcs(A4 + base4 + 128 + k * 32 + lane);
    drain();
    #pragma unroll
    for (int k = 0; k < 4; k++) compact(av[k], base4 + 128 + k * 32 + lane);
    drain();

    // block reduce (acc lives on lanes 0 and 16)
    #pragma unroll
    for (int off = 16; off > 0; off >>= 1)
        acc += __shfl_xor_sync(FULLM, acc, off);
    if (lane == 0) sp[w] = acc;
    __syncthreads();

    if (threadIdx.x == 0) {
        float part = 0.f;
        #pragma unroll
        for (int i = 0; i < 8; i++) part += sp[i];
        atomicAdd(&g_sum, part);
        __threadfence();
        unsigned c = atomicAdd(&g_count, 1u);
        if (c == gridDim.x - 1) {
            float total = atomicExch(&g_sum, 0.f);
            atomicExch(&g_count, 0u);
            out[0] = total;
        }
    }
}

extern "C" void kernel_launch(void* const* d_in, const int* in_sizes, int n_in,
                              void* d_out, int out_size) {
    const float* A = (const float*)d_in[0];
    const float* W = (const float*)d_in[1];
    const float* b = (const float*)d_in[2];
    float* out = (float*)d_out;

    main_kernel<<<GN, 256>>>(A, W, b, out);
}